// round 3
// baseline (speedup 1.0000x reference)
#include <cuda_runtime.h>
#include <cstdint>

// ---------------------------------------------------------------------------
// Problem constants
// ---------------------------------------------------------------------------
#define T_TOKENS 4096
#define DDIM 1024
#define FDIM 4096
#define NEXP 8
#define BM 128
#define BN 128
#define BK 16
#define MAX_MT 72
#define ROWS_CAP (MAX_MT * 128)

// ---------------------------------------------------------------------------
// Device scratch (static __device__ arrays — allocation-free)
// ---------------------------------------------------------------------------
__device__ int   g_cnt[NEXP];
__device__ int   g_cur[NEXP];
__device__ int   g_nmt;
__device__ int   g_tile_e[MAX_MT];
__device__ int   g_tile_r[MAX_MT];
__device__ int   g_row_token[ROWS_CAP];
__device__ int   g_tok_e[T_TOKENS * 2];
__device__ int   g_tok_row[T_TOKENS * 2];
__device__ float g_tok_w[T_TOKENS * 2];
__device__ float g_H[(size_t)ROWS_CAP * FDIM];   // SwiGLU intermediate
__device__ float g_Y[(size_t)ROWS_CAP * DDIM];   // per-(token,expert) output rows

// ---------------------------------------------------------------------------
// Helpers
// ---------------------------------------------------------------------------
__device__ __forceinline__ uint32_t smem_u32(const void* p) {
    uint32_t a;
    asm("{ .reg .u64 t; cvta.to.shared.u64 t, %1; cvt.u32.u64 %0, t; }" : "=r"(a) : "l"(p));
    return a;
}
__device__ __forceinline__ uint32_t tf32u(float f) {   // round-to-nearest tf32 (bits)
    uint32_t u = __float_as_uint(f);
    asm("cvt.rna.tf32.f32 %0, %0;" : "+r"(u));
    return u;
}
__device__ __forceinline__ uint32_t lds32(uint32_t a) {
    uint32_t v;
    asm volatile("ld.shared.b32 %0, [%1];" : "=r"(v) : "r"(a));
    return v;
}
__device__ __forceinline__ void sts128(uint32_t a, uint32_t x, uint32_t y, uint32_t z, uint32_t w) {
    asm volatile("st.shared.v4.b32 [%0], {%1,%2,%3,%4};" :: "r"(a), "r"(x), "r"(y), "r"(z), "r"(w));
}
// m16n8k8 tf32 HMMA (base ISA, works on plain sm_103 target)
__device__ __forceinline__ void mma8(float* d, const uint32_t* a, uint32_t b0, uint32_t b1) {
    asm volatile(
        "mma.sync.aligned.m16n8k8.row.col.f32.tf32.tf32.f32 "
        "{%0,%1,%2,%3}, {%4,%5,%6,%7}, {%8,%9}, {%0,%1,%2,%3};"
        : "+f"(d[0]), "+f"(d[1]), "+f"(d[2]), "+f"(d[3])
        : "r"(a[0]), "r"(a[1]), "r"(a[2]), "r"(a[3]), "r"(b0), "r"(b1));
}

// Smem tile layout: [row][BK] floats, 64B rows, SW64 swizzle within the row.
// staged byte offset for 16B chunk c of row r:  r*64 + (c*16 ^ ((r&6)<<3))
// fragment byte offset for k-scalar of row r:   r*64 + ((k*4) ^ ((r&6)<<3))
// Both verified conflict-free (32 distinct banks per warp access).

#define STAGE1_SZ 24576   // A(8K) + B1(8K) + B3(8K)
#define STAGE2_SZ 16384   // A(8K) + B(8K)
#define SMEM1_SZ (1024 + 2 * STAGE1_SZ)
#define SMEM2_SZ (1024 + 2 * STAGE2_SZ)

// ---------------------------------------------------------------------------
// K1: init
// ---------------------------------------------------------------------------
__global__ void init_kernel() {
    if (threadIdx.x < NEXP) g_cnt[threadIdx.x] = 0;
}

// ---------------------------------------------------------------------------
// K2: router — one warp per token; top-2 renorm weight = sigmoid(l0 - l1)
// ---------------------------------------------------------------------------
__global__ void router_kernel(const float* __restrict__ x, const float* __restrict__ rw,
                              const float* __restrict__ rb) {
    int warp = (blockIdx.x * blockDim.x + threadIdx.x) >> 5;
    int lane = threadIdx.x & 31;
    if (warp >= T_TOKENS) return;
    const float* xt = x + (size_t)warp * DDIM;
    float acc[NEXP];
#pragma unroll
    for (int e = 0; e < NEXP; e++) acc[e] = 0.f;
    for (int i = lane; i < DDIM; i += 32) {
        float xv = xt[i];
#pragma unroll
        for (int e = 0; e < NEXP; e++) acc[e] += xv * rw[e * DDIM + i];
    }
#pragma unroll
    for (int off = 16; off; off >>= 1)
#pragma unroll
        for (int e = 0; e < NEXP; e++) acc[e] += __shfl_xor_sync(0xffffffffu, acc[e], off);
    if (lane == 0) {
#pragma unroll
        for (int e = 0; e < NEXP; e++) acc[e] += rb[e];
        int e0 = 0; float l0 = acc[0];
#pragma unroll
        for (int e = 1; e < NEXP; e++) if (acc[e] > l0) { l0 = acc[e]; e0 = e; }
        int e1 = (e0 == 0) ? 1 : 0; float l1 = acc[e1];
#pragma unroll
        for (int e = 0; e < NEXP; e++)
            if (e != e0 && acc[e] > l1) { l1 = acc[e]; e1 = e; }
        float w0 = 1.f / (1.f + __expf(l1 - l0));
        g_tok_e[2 * warp] = e0;  g_tok_e[2 * warp + 1] = e1;
        g_tok_w[2 * warp] = w0;  g_tok_w[2 * warp + 1] = 1.f - w0;
        atomicAdd(&g_cnt[e0], 1);
        atomicAdd(&g_cnt[e1], 1);
    }
}

// ---------------------------------------------------------------------------
// K3: scan — 128-aligned segments + m-tile map
// ---------------------------------------------------------------------------
__global__ void scan_kernel() {
    if (threadIdx.x != 0) return;
    int base = 0, nt = 0;
    for (int e = 0; e < NEXP; e++) {
        g_cur[e] = base;
        int tiles = (g_cnt[e] + 127) >> 7;
        for (int i = 0; i < tiles; i++) { g_tile_e[nt] = e; g_tile_r[nt] = base + i * 128; nt++; }
        base += tiles << 7;
    }
    g_nmt = nt;
}

// ---------------------------------------------------------------------------
// K4: scatter token -> row
// ---------------------------------------------------------------------------
__global__ void scatter_kernel() {
    int t = blockIdx.x * blockDim.x + threadIdx.x;
    if (t >= T_TOKENS) return;
#pragma unroll
    for (int k = 0; k < 2; k++) {
        int e = g_tok_e[2 * t + k];
        int r = atomicAdd(&g_cur[e], 1);
        g_row_token[r] = t;
        g_tok_row[2 * t + k] = r;
    }
}

// ---------------------------------------------------------------------------
// K5: grouped GEMM1 — H = silu(X@w1) * (X@w3)
// CTA tile 128x128, BK=16, 8 warps (2M x 4N), warp tile 64x32, both gates.
// ---------------------------------------------------------------------------
__global__ void __launch_bounds__(256, 1)
gemm1_kernel(const float* __restrict__ x, const float* __restrict__ w1,
             const float* __restrict__ w3) {
    if (blockIdx.x >= g_nmt) return;
    extern __shared__ char smem[];
    const uint32_t sb = smem_u32(smem);
    const int tid = threadIdx.x, wid = tid >> 5, lane = tid & 31;
    const int wm = wid >> 2, wn = wid & 3;
    const int r4 = lane >> 2, c4 = lane & 3;
    const uint32_t xa = (uint32_t)((r4 & 6) << 3);

    const int e  = g_tile_e[blockIdx.x];
    const int r0 = g_tile_r[blockIdx.x];
    const int n0 = blockIdx.y * BN;

    int* s_tok = (int*)smem;
    if (tid < 128) {
        int t = g_row_token[r0 + tid];
        s_tok[tid] = ((unsigned)t < T_TOKENS) ? t : 0;
    }
    __syncthreads();

    const float* w1e = w1 + (size_t)e * DDIM * FDIM + n0;
    const float* w3e = w3 + (size_t)e * DDIM * FDIM + n0;

    // ---- per-thread staging addresses ----
    const float* pA[2]; uint32_t stA[2];
#pragma unroll
    for (int i = 0; i < 2; i++) {
        int idx = tid + i * 256;
        int row = idx >> 2, c = idx & 3;
        pA[i]  = x + (size_t)s_tok[row] * DDIM + c * 4;
        stA[i] = row * 64 + ((c * 16) ^ ((row & 6) << 3));
    }
    const float* pB1[2]; const float* pB3[2]; uint32_t stB[2];
#pragma unroll
    for (int i = 0; i < 2; i++) {
        int idx = tid + i * 256;
        int n = idx & 127, c = idx >> 7;
        pB1[i] = w1e + (size_t)(c * 4) * FDIM + n;
        pB3[i] = w3e + (size_t)(c * 4) * FDIM + n;
        stB[i] = n * 64 + ((c * 16) ^ ((n & 6) << 3));
    }

    float accU[4][4][4], accV[4][4][4];
#pragma unroll
    for (int i = 0; i < 4; i++)
#pragma unroll
        for (int j = 0; j < 4; j++)
#pragma unroll
            for (int q = 0; q < 4; q++) { accU[i][j][q] = 0.f; accV[i][j][q] = 0.f; }

    float4 rA[2]; float rB1[2][4], rB3[2][4];
    const int KS = DDIM / BK;   // 64

    // prologue: stage step 0
#pragma unroll
    for (int i = 0; i < 2; i++) {
        rA[i] = *(const float4*)pA[i];
#pragma unroll
        for (int j = 0; j < 4; j++) { rB1[i][j] = pB1[i][(size_t)j * FDIM]; rB3[i][j] = pB3[i][(size_t)j * FDIM]; }
    }
#pragma unroll
    for (int i = 0; i < 2; i++) {
        uint32_t sA = sb + 1024, sB1 = sA + 8192, sB3 = sA + 16384;
        sts128(sA + stA[i], tf32u(rA[i].x), tf32u(rA[i].y), tf32u(rA[i].z), tf32u(rA[i].w));
        sts128(sB1 + stB[i], tf32u(rB1[i][0]), tf32u(rB1[i][1]), tf32u(rB1[i][2]), tf32u(rB1[i][3]));
        sts128(sB3 + stB[i], tf32u(rB3[i][0]), tf32u(rB3[i][1]), tf32u(rB3[i][2]), tf32u(rB3[i][3]));
    }
    __syncthreads();

    for (int ks = 0; ks < KS; ks++) {
        // issue next step's gmem loads
        if (ks + 1 < KS) {
            const size_t koffA = (size_t)(ks + 1) * BK;
            const size_t koffB = (size_t)(ks + 1) * BK * FDIM;
#pragma unroll
            for (int i = 0; i < 2; i++) {
                rA[i] = *(const float4*)(pA[i] + koffA);
#pragma unroll
                for (int j = 0; j < 4; j++) {
                    rB1[i][j] = pB1[i][koffB + (size_t)j * FDIM];
                    rB3[i][j] = pB3[i][koffB + (size_t)j * FDIM];
                }
            }
        }
        // MMA on current buffer
        {
            const uint32_t sA  = sb + 1024 + (ks & 1) * STAGE1_SZ;
            const uint32_t sB1 = sA + 8192;
            const uint32_t sB3 = sA + 16384;
#pragma unroll
            for (int k8 = 0; k8 < 2; k8++) {
                const uint32_t k0 = (uint32_t)((k8 * 8 + c4) * 4);
                const uint32_t k1 = k0 + 16;
                uint32_t a[4][4];
#pragma unroll
                for (int mt = 0; mt < 4; mt++) {
                    uint32_t rowb = sA + (uint32_t)((wm * 64 + mt * 16 + r4) * 64);
                    a[mt][0] = lds32(rowb + (k0 ^ xa));
                    a[mt][1] = lds32(rowb + 512 + (k0 ^ xa));
                    a[mt][2] = lds32(rowb + (k1 ^ xa));
                    a[mt][3] = lds32(rowb + 512 + (k1 ^ xa));
                }
#pragma unroll
                for (int nt = 0; nt < 4; nt++) {
                    uint32_t nrow = (uint32_t)((wn * 32 + nt * 8 + r4) * 64);
                    uint32_t b0 = lds32(sB1 + nrow + (k0 ^ xa));
                    uint32_t b1 = lds32(sB1 + nrow + (k1 ^ xa));
                    uint32_t d0 = lds32(sB3 + nrow + (k0 ^ xa));
                    uint32_t d1 = lds32(sB3 + nrow + (k1 ^ xa));
#pragma unroll
                    for (int mt = 0; mt < 4; mt++) {
                        mma8(accU[mt][nt], a[mt], b0, b1);
                        mma8(accV[mt][nt], a[mt], d0, d1);
                    }
                }
            }
        }
        // store next buffer
        if (ks + 1 < KS) {
            const uint32_t sA  = sb + 1024 + ((ks + 1) & 1) * STAGE1_SZ;
            const uint32_t sB1 = sA + 8192;
            const uint32_t sB3 = sA + 16384;
#pragma unroll
            for (int i = 0; i < 2; i++) {
                sts128(sA + stA[i], tf32u(rA[i].x), tf32u(rA[i].y), tf32u(rA[i].z), tf32u(rA[i].w));
                sts128(sB1 + stB[i], tf32u(rB1[i][0]), tf32u(rB1[i][1]), tf32u(rB1[i][2]), tf32u(rB1[i][3]));
                sts128(sB3 + stB[i], tf32u(rB3[i][0]), tf32u(rB3[i][1]), tf32u(rB3[i][2]), tf32u(rB3[i][3]));
            }
        }
        __syncthreads();
    }

    // epilogue: h = silu(u) * v, write g_H
#pragma unroll
    for (int mt = 0; mt < 4; mt++) {
#pragma unroll
        for (int nt = 0; nt < 4; nt++) {
#pragma unroll
            for (int half = 0; half < 2; half++) {
                int r = r0 + wm * 64 + mt * 16 + r4 + half * 8;
                int cgl = n0 + wn * 32 + nt * 8 + 2 * c4;
                float u0 = accU[mt][nt][2 * half],     v0 = accV[mt][nt][2 * half];
                float u1 = accU[mt][nt][2 * half + 1], v1 = accV[mt][nt][2 * half + 1];
                float2 o;
                o.x = u0 / (1.f + __expf(-u0)) * v0;
                o.y = u1 / (1.f + __expf(-u1)) * v1;
                *(float2*)(g_H + (size_t)r * FDIM + cgl) = o;
            }
        }
    }
}

// ---------------------------------------------------------------------------
// K6: grouped GEMM2 — Y = H @ w2
// ---------------------------------------------------------------------------
__global__ void __launch_bounds__(256, 1)
gemm2_kernel(const float* __restrict__ w2) {
    if (blockIdx.x >= g_nmt) return;
    extern __shared__ char smem[];
    const uint32_t sb = smem_u32(smem);
    const int tid = threadIdx.x, wid = tid >> 5, lane = tid & 31;
    const int wm = wid >> 2, wn = wid & 3;
    const int r4 = lane >> 2, c4 = lane & 3;
    const uint32_t xa = (uint32_t)((r4 & 6) << 3);

    const int e  = g_tile_e[blockIdx.x];
    const int r0 = g_tile_r[blockIdx.x];
    const int n0 = blockIdx.y * BN;

    const float* w2e = w2 + (size_t)e * FDIM * DDIM + n0;

    const float* pA[2]; uint32_t stA[2];
#pragma unroll
    for (int i = 0; i < 2; i++) {
        int idx = tid + i * 256;
        int row = idx >> 2, c = idx & 3;
        pA[i]  = g_H + (size_t)(r0 + row) * FDIM + c * 4;
        stA[i] = row * 64 + ((c * 16) ^ ((row & 6) << 3));
    }
    const float* pB[2]; uint32_t stB[2];
#pragma unroll
    for (int i = 0; i < 2; i++) {
        int idx = tid + i * 256;
        int n = idx & 127, c = idx >> 7;
        pB[i]  = w2e + (size_t)(c * 4) * DDIM + n;
        stB[i] = n * 64 + ((c * 16) ^ ((n & 6) << 3));
    }

    float acc[4][4][4];
#pragma unroll
    for (int i = 0; i < 4; i++)
#pragma unroll
        for (int j = 0; j < 4; j++)
#pragma unroll
            for (int q = 0; q < 4; q++) acc[i][j][q] = 0.f;

    float4 rA[2]; float rB[2][4];
    const int KS = FDIM / BK;   // 256

#pragma unroll
    for (int i = 0; i < 2; i++) {
        rA[i] = *(const float4*)pA[i];
#pragma unroll
        for (int j = 0; j < 4; j++) rB[i][j] = pB[i][(size_t)j * DDIM];
    }
#pragma unroll
    for (int i = 0; i < 2; i++) {
        uint32_t sA = sb + 1024, sB = sA + 8192;
        sts128(sA + stA[i], tf32u(rA[i].x), tf32u(rA[i].y), tf32u(rA[i].z), tf32u(rA[i].w));
        sts128(sB + stB[i], tf32u(rB[i][0]), tf32u(rB[i][1]), tf32u(rB[i][2]), tf32u(rB[i][3]));
    }
    __syncthreads();

    for (int ks = 0; ks < KS; ks++) {
        if (ks + 1 < KS) {
            const size_t koffA = (size_t)(ks + 1) * BK;
            const size_t koffB = (size_t)(ks + 1) * BK * DDIM;
#pragma unroll
            for (int i = 0; i < 2; i++) {
                rA[i] = *(const float4*)(pA[i] + koffA);
#pragma unroll
                for (int j = 0; j < 4; j++) rB[i][j] = pB[i][koffB + (size_t)j * DDIM];
            }
        }
        {
            const uint32_t sA = sb + 1024 + (ks & 1) * STAGE2_SZ;
            const uint32_t sB = sA + 8192;
#pragma unroll
            for (int k8 = 0; k8 < 2; k8++) {
                const uint32_t k0 = (uint32_t)((k8 * 8 + c4) * 4);
                const uint32_t k1 = k0 + 16;
                uint32_t a[4][4];
#pragma unroll
                for (int mt = 0; mt < 4; mt++) {
                    uint32_t rowb = sA + (uint32_t)((wm * 64 + mt * 16 + r4) * 64);
                    a[mt][0] = lds32(rowb + (k0 ^ xa));
                    a[mt][1] = lds32(rowb + 512 + (k0 ^ xa));
                    a[mt][2] = lds32(rowb + (k1 ^ xa));
                    a[mt][3] = lds32(rowb + 512 + (k1 ^ xa));
                }
#pragma unroll
                for (int nt = 0; nt < 4; nt++) {
                    uint32_t nrow = (uint32_t)((wn * 32 + nt * 8 + r4) * 64);
                    uint32_t b0 = lds32(sB + nrow + (k0 ^ xa));
                    uint32_t b1 = lds32(sB + nrow + (k1 ^ xa));
#pragma unroll
                    for (int mt = 0; mt < 4; mt++) mma8(acc[mt][nt], a[mt], b0, b1);
                }
            }
        }
        if (ks + 1 < KS) {
            const uint32_t sA = sb + 1024 + ((ks + 1) & 1) * STAGE2_SZ;
            const uint32_t sB = sA + 8192;
#pragma unroll
            for (int i = 0; i < 2; i++) {
                sts128(sA + stA[i], tf32u(rA[i].x), tf32u(rA[i].y), tf32u(rA[i].z), tf32u(rA[i].w));
                sts128(sB + stB[i], tf32u(rB[i][0]), tf32u(rB[i][1]), tf32u(rB[i][2]), tf32u(rB[i][3]));
            }
        }
        __syncthreads();
    }

#pragma unroll
    for (int mt = 0; mt < 4; mt++) {
#pragma unroll
        for (int nt = 0; nt < 4; nt++) {
#pragma unroll
            for (int half = 0; half < 2; half++) {
                int r = r0 + wm * 64 + mt * 16 + r4 + half * 8;
                int cgl = n0 + wn * 32 + nt * 8 + 2 * c4;
                float2 o;
                o.x = acc[mt][nt][2 * half];
                o.y = acc[mt][nt][2 * half + 1];
                *(float2*)(g_Y + (size_t)r * DDIM + cgl) = o;
            }
        }
    }
}

// ---------------------------------------------------------------------------
// K7: combine — out[t] = w0*Y[row0] + w1*Y[row1]
// ---------------------------------------------------------------------------
__global__ void combine_kernel(float* __restrict__ out) {
    int t = blockIdx.x;
    int d = threadIdx.x * 4;
    float w0 = g_tok_w[2 * t], w1v = g_tok_w[2 * t + 1];
    int   r0 = g_tok_row[2 * t], r1 = g_tok_row[2 * t + 1];
    const float4 a = *(const float4*)(g_Y + (size_t)r0 * DDIM + d);
    const float4 b = *(const float4*)(g_Y + (size_t)r1 * DDIM + d);
    float4 o;
    o.x = w0 * a.x + w1v * b.x;
    o.y = w0 * a.y + w1v * b.y;
    o.z = w0 * a.z + w1v * b.z;
    o.w = w0 * a.w + w1v * b.w;
    *(float4*)(out + (size_t)t * DDIM + d) = o;
}

// ---------------------------------------------------------------------------
// Launcher
// ---------------------------------------------------------------------------
extern "C" void kernel_launch(void* const* d_in, const int* in_sizes, int n_in,
                              void* d_out, int out_size) {
    const float* x  = (const float*)d_in[0];
    const float* rw = (const float*)d_in[1];
    const float* rb = (const float*)d_in[2];
    const float* w1 = (const float*)d_in[3];
    const float* w2 = (const float*)d_in[4];
    const float* w3 = (const float*)d_in[5];
    float* out = (float*)d_out;

    cudaFuncSetAttribute(gemm1_kernel, cudaFuncAttributeMaxDynamicSharedMemorySize, SMEM1_SZ);
    cudaFuncSetAttribute(gemm2_kernel, cudaFuncAttributeMaxDynamicSharedMemorySize, SMEM2_SZ);

    init_kernel<<<1, 32>>>();
    router_kernel<<<(T_TOKENS * 32) / 256, 256>>>(x, rw, rb);
    scan_kernel<<<1, 1>>>();
    scatter_kernel<<<T_TOKENS / 256, 256>>>();
    gemm1_kernel<<<dim3(MAX_MT, FDIM / BN), 256, SMEM1_SZ>>>(x, w1, w3);
    gemm2_kernel<<<dim3(MAX_MT, DDIM / BN), 256, SMEM2_SZ>>>(w2);
    combine_kernel<<<T_TOKENS, 256>>>(out);
}

// round 4
// speedup vs baseline: 1.3163x; 1.3163x over previous
#include <cuda_runtime.h>
#include <cstdint>

// ---------------------------------------------------------------------------
// Problem constants
// ---------------------------------------------------------------------------
#define T_TOKENS 4096
#define DDIM 1024
#define FDIM 4096
#define NEXP 8
#define BM 128
#define BN 128
#define BK 16
#define MAX_MT 72
#define ROWS_CAP (MAX_MT * 128)

// ---------------------------------------------------------------------------
// Device scratch (static __device__ arrays — allocation-free)
// ---------------------------------------------------------------------------
__device__ int   g_cnt[NEXP];
__device__ int   g_cur[NEXP];
__device__ int   g_nmt;
__device__ int   g_tile_e[MAX_MT];
__device__ int   g_tile_r[MAX_MT];
__device__ int   g_row_token[ROWS_CAP];
__device__ int   g_tok_e[T_TOKENS * 2];
__device__ int   g_tok_row[T_TOKENS * 2];
__device__ float g_tok_w[T_TOKENS * 2];
__device__ float g_H[(size_t)ROWS_CAP * FDIM];          // SwiGLU intermediate (tf32-rounded)
__device__ float g_Y[(size_t)ROWS_CAP * DDIM];          // per-(token,expert) outputs
__device__ float g_xt[(size_t)T_TOKENS * DDIM];         // x, tf32-rounded
__device__ float g_w1t[(size_t)NEXP * DDIM * FDIM];     // w1^T [E][F][D], rounded
__device__ float g_w3t[(size_t)NEXP * DDIM * FDIM];     // w3^T [E][F][D], rounded
__device__ float g_w2t[(size_t)NEXP * DDIM * FDIM];     // w2^T [E][D][F], rounded

// ---------------------------------------------------------------------------
// Helpers
// ---------------------------------------------------------------------------
__device__ __forceinline__ uint32_t smem_u32(const void* p) {
    uint32_t a;
    asm("{ .reg .u64 t; cvta.to.shared.u64 t, %1; cvt.u32.u64 %0, t; }" : "=r"(a) : "l"(p));
    return a;
}
__device__ __forceinline__ uint32_t tf32u(float f) {   // round-to-nearest tf32 (bits)
    uint32_t u = __float_as_uint(f);
    asm("cvt.rna.tf32.f32 %0, %0;" : "+r"(u));
    return u;
}
__device__ __forceinline__ uint32_t lds32(uint32_t a) {
    uint32_t v;
    asm volatile("ld.shared.b32 %0, [%1];" : "=r"(v) : "r"(a));
    return v;
}
__device__ __forceinline__ void mma8(float* d, const uint32_t* a, uint32_t b0, uint32_t b1) {
    asm volatile(
        "mma.sync.aligned.m16n8k8.row.col.f32.tf32.tf32.f32 "
        "{%0,%1,%2,%3}, {%4,%5,%6,%7}, {%8,%9}, {%0,%1,%2,%3};"
        : "+f"(d[0]), "+f"(d[1]), "+f"(d[2]), "+f"(d[3])
        : "r"(a[0]), "r"(a[1]), "r"(a[2]), "r"(a[3]), "r"(b0), "r"(b1));
}
#define CP_ASYNC16(dst, src) \
    asm volatile("cp.async.cg.shared.global [%0], [%1], 16;" :: "r"(dst), "l"(src))
#define CP_COMMIT() asm volatile("cp.async.commit_group;" ::: "memory")
#define CP_WAIT1()  asm volatile("cp.async.wait_group 1;" ::: "memory")

// Smem tile: [row][16 floats] = 64B rows, SW64 swizzle.
//   staged 16B chunk c of row r : r*64 + (c*16 ^ ((r&6)<<3))
//   fragment scalar k of row r  : r*64 + ((k*4) ^ ((r&6)<<3))
// Both conflict-free (verified R3).
#define STAGE1_SZ 24576   // A(8K) + B1(8K) + B3(8K)
#define STAGE2_SZ 16384   // A(8K) + B(8K)
#define SMEM1_SZ (1024 + 3 * STAGE1_SZ)
#define SMEM2_SZ (1024 + 3 * STAGE2_SZ)

// ---------------------------------------------------------------------------
// K0a: convert x -> tf32-rounded
// ---------------------------------------------------------------------------
__global__ void convx_kernel(const float* __restrict__ x) {
    int i = blockIdx.x * blockDim.x + threadIdx.x;
    float4 v = ((const float4*)x)[i];
    uint4 o;
    o.x = tf32u(v.x); o.y = tf32u(v.y); o.z = tf32u(v.z); o.w = tf32u(v.w);
    ((uint4*)g_xt)[i] = o;
}

// ---------------------------------------------------------------------------
// K0b: transpose + round: src [Z][R][C] -> dst [Z][C][R]
// ---------------------------------------------------------------------------
__global__ void transpose_kernel(const float* __restrict__ src, float* __restrict__ dst,
                                 int R, int C) {
    __shared__ float t[32][33];
    const size_t mo = (size_t)blockIdx.z * R * C;
    const int c0 = blockIdx.x * 32, r0 = blockIdx.y * 32;
    const int tx = threadIdx.x, ty = threadIdx.y;
#pragma unroll
    for (int i = 0; i < 32; i += 8)
        t[ty + i][tx] = src[mo + (size_t)(r0 + ty + i) * C + c0 + tx];
    __syncthreads();
#pragma unroll
    for (int i = 0; i < 32; i += 8)
        dst[mo + (size_t)(c0 + ty + i) * R + r0 + tx] = __uint_as_float(tf32u(t[tx][ty + i]));
}

// ---------------------------------------------------------------------------
// K1: init
// ---------------------------------------------------------------------------
__global__ void init_kernel() {
    if (threadIdx.x < NEXP) g_cnt[threadIdx.x] = 0;
}

// ---------------------------------------------------------------------------
// K2: router — one warp per token; top-2 renorm weight = sigmoid(l0 - l1)
// ---------------------------------------------------------------------------
__global__ void router_kernel(const float* __restrict__ x, const float* __restrict__ rw,
                              const float* __restrict__ rb) {
    int warp = (blockIdx.x * blockDim.x + threadIdx.x) >> 5;
    int lane = threadIdx.x & 31;
    if (warp >= T_TOKENS) return;
    const float* xt = x + (size_t)warp * DDIM;
    float acc[NEXP];
#pragma unroll
    for (int e = 0; e < NEXP; e++) acc[e] = 0.f;
    for (int i = lane; i < DDIM; i += 32) {
        float xv = xt[i];
#pragma unroll
        for (int e = 0; e < NEXP; e++) acc[e] += xv * rw[e * DDIM + i];
    }
#pragma unroll
    for (int off = 16; off; off >>= 1)
#pragma unroll
        for (int e = 0; e < NEXP; e++) acc[e] += __shfl_xor_sync(0xffffffffu, acc[e], off);
    if (lane == 0) {
#pragma unroll
        for (int e = 0; e < NEXP; e++) acc[e] += rb[e];
        int e0 = 0; float l0 = acc[0];
#pragma unroll
        for (int e = 1; e < NEXP; e++) if (acc[e] > l0) { l0 = acc[e]; e0 = e; }
        int e1 = (e0 == 0) ? 1 : 0; float l1 = acc[e1];
#pragma unroll
        for (int e = 0; e < NEXP; e++)
            if (e != e0 && acc[e] > l1) { l1 = acc[e]; e1 = e; }
        float w0 = 1.f / (1.f + __expf(l1 - l0));
        g_tok_e[2 * warp] = e0;  g_tok_e[2 * warp + 1] = e1;
        g_tok_w[2 * warp] = w0;  g_tok_w[2 * warp + 1] = 1.f - w0;
        atomicAdd(&g_cnt[e0], 1);
        atomicAdd(&g_cnt[e1], 1);
    }
}

// ---------------------------------------------------------------------------
// K3: scan — 128-aligned segments + m-tile map
// ---------------------------------------------------------------------------
__global__ void scan_kernel() {
    if (threadIdx.x != 0) return;
    int base = 0, nt = 0;
    for (int e = 0; e < NEXP; e++) {
        g_cur[e] = base;
        int tiles = (g_cnt[e] + 127) >> 7;
        for (int i = 0; i < tiles; i++) { g_tile_e[nt] = e; g_tile_r[nt] = base + i * 128; nt++; }
        base += tiles << 7;
    }
    g_nmt = nt;
}

// ---------------------------------------------------------------------------
// K4: scatter token -> row
// ---------------------------------------------------------------------------
__global__ void scatter_kernel() {
    int t = blockIdx.x * blockDim.x + threadIdx.x;
    if (t >= T_TOKENS) return;
#pragma unroll
    for (int k = 0; k < 2; k++) {
        int e = g_tok_e[2 * t + k];
        int r = atomicAdd(&g_cur[e], 1);
        g_row_token[r] = t;
        g_tok_row[2 * t + k] = r;
    }
}

// ---------------------------------------------------------------------------
// K5: grouped GEMM1 — H = silu(X@w1) * (X@w3)
// 128x128 CTA tile, BK=16, 8 warps (2Mx4N), cp.async 3-stage pipeline.
// ---------------------------------------------------------------------------
__global__ void __launch_bounds__(256, 1)
gemm1_kernel() {
    if (blockIdx.x >= g_nmt) return;
    extern __shared__ char smem[];
    const uint32_t sb = smem_u32(smem);
    const int tid = threadIdx.x, wid = tid >> 5, lane = tid & 31;
    const int wm = wid >> 2, wn = wid & 3;
    const int r4 = lane >> 2, c4 = lane & 3;
    const uint32_t xa = (uint32_t)((r4 & 6) << 3);

    const int e  = g_tile_e[blockIdx.x];
    const int r0 = g_tile_r[blockIdx.x];
    const int n0 = blockIdx.y * BN;

    int* s_tok = (int*)smem;
    if (tid < 128) {
        int t = g_row_token[r0 + tid];
        s_tok[tid] = ((unsigned)t < T_TOKENS) ? t : 0;
    }
    __syncthreads();

    const float* w1e = g_w1t + (size_t)e * FDIM * DDIM + (size_t)n0 * DDIM;
    const float* w3e = g_w3t + (size_t)e * FDIM * DDIM + (size_t)n0 * DDIM;

    // per-thread cp.async chunk assignment (2 chunks per region)
    const char* srcA[2]; const char* srcB1[2]; const char* srcB3[2];
    uint32_t dA[2], dB[2];
#pragma unroll
    for (int i = 0; i < 2; i++) {
        int idx = tid + i * 256;
        int row = idx >> 2, c = idx & 3;                 // A: row 0..127, chunk 0..3
        srcA[i] = (const char*)(g_xt + (size_t)s_tok[row] * DDIM + c * 4);
        dA[i]   = row * 64 + ((c * 16) ^ ((row & 6) << 3));
        int n = idx & 127, cb = idx >> 7;                // B: n 0..127, chunk 0..3
        srcB1[i] = (const char*)(w1e + (size_t)n * DDIM + cb * 4);
        srcB3[i] = (const char*)(w3e + (size_t)n * DDIM + cb * 4);
        dB[i]    = n * 64 + ((cb * 16) ^ ((n & 6) << 3));
    }

    float accU[4][4][4], accV[4][4][4];
#pragma unroll
    for (int i = 0; i < 4; i++)
#pragma unroll
        for (int j = 0; j < 4; j++)
#pragma unroll
            for (int q = 0; q < 4; q++) { accU[i][j][q] = 0.f; accV[i][j][q] = 0.f; }

    const int KS = DDIM / BK;   // 64

#define G1_ISSUE(s)                                                            \
    do {                                                                       \
        uint32_t base_ = sb + 1024 + ((s) % 3) * STAGE1_SZ;                    \
        size_t off_ = (size_t)(s) * 64;                                        \
        _Pragma("unroll")                                                      \
        for (int i_ = 0; i_ < 2; i_++) {                                       \
            CP_ASYNC16(base_ + dA[i_],          srcA[i_]  + off_);             \
            CP_ASYNC16(base_ + 8192  + dB[i_],  srcB1[i_] + off_);             \
            CP_ASYNC16(base_ + 16384 + dB[i_],  srcB3[i_] + off_);             \
        }                                                                      \
    } while (0)

    G1_ISSUE(0); CP_COMMIT();
    G1_ISSUE(1); CP_COMMIT();

    for (int ks = 0; ks < KS; ks++) {
        CP_WAIT1();
        __syncthreads();
        if (ks + 2 < KS) G1_ISSUE(ks + 2);
        CP_COMMIT();

        const uint32_t sA  = sb + 1024 + (ks % 3) * STAGE1_SZ;
        const uint32_t sB1 = sA + 8192;
        const uint32_t sB3 = sA + 16384;
#pragma unroll
        for (int k8 = 0; k8 < 2; k8++) {
            const uint32_t k0 = (uint32_t)((k8 * 8 + c4) * 4);
            const uint32_t k1 = k0 + 16;
            uint32_t a[4][4];
#pragma unroll
            for (int mt = 0; mt < 4; mt++) {
                uint32_t rowb = sA + (uint32_t)((wm * 64 + mt * 16 + r4) * 64);
                a[mt][0] = lds32(rowb + (k0 ^ xa));
                a[mt][1] = lds32(rowb + 512 + (k0 ^ xa));
                a[mt][2] = lds32(rowb + (k1 ^ xa));
                a[mt][3] = lds32(rowb + 512 + (k1 ^ xa));
            }
#pragma unroll
            for (int nt = 0; nt < 4; nt++) {
                uint32_t nrow = (uint32_t)((wn * 32 + nt * 8 + r4) * 64);
                uint32_t b0 = lds32(sB1 + nrow + (k0 ^ xa));
                uint32_t b1 = lds32(sB1 + nrow + (k1 ^ xa));
                uint32_t d0 = lds32(sB3 + nrow + (k0 ^ xa));
                uint32_t d1 = lds32(sB3 + nrow + (k1 ^ xa));
#pragma unroll
                for (int mt = 0; mt < 4; mt++) {
                    mma8(accU[mt][nt], a[mt], b0, b1);
                    mma8(accV[mt][nt], a[mt], d0, d1);
                }
            }
        }
    }

    // epilogue: h = silu(u)*v, tf32-rounded, write g_H
#pragma unroll
    for (int mt = 0; mt < 4; mt++) {
#pragma unroll
        for (int nt = 0; nt < 4; nt++) {
#pragma unroll
            for (int half = 0; half < 2; half++) {
                int r = r0 + wm * 64 + mt * 16 + r4 + half * 8;
                int cgl = n0 + wn * 32 + nt * 8 + 2 * c4;
                float u0 = accU[mt][nt][2 * half],     v0 = accV[mt][nt][2 * half];
                float u1 = accU[mt][nt][2 * half + 1], v1 = accV[mt][nt][2 * half + 1];
                float2 o;
                o.x = __uint_as_float(tf32u(u0 / (1.f + __expf(-u0)) * v0));
                o.y = __uint_as_float(tf32u(u1 / (1.f + __expf(-u1)) * v1));
                *(float2*)(g_H + (size_t)r * FDIM + cgl) = o;
            }
        }
    }
}

// ---------------------------------------------------------------------------
// K6: grouped GEMM2 — Y = H @ w2
// ---------------------------------------------------------------------------
__global__ void __launch_bounds__(256, 2)
gemm2_kernel() {
    if (blockIdx.x >= g_nmt) return;
    extern __shared__ char smem[];
    const uint32_t sb = smem_u32(smem);
    const int tid = threadIdx.x, wid = tid >> 5, lane = tid & 31;
    const int wm = wid >> 2, wn = wid & 3;
    const int r4 = lane >> 2, c4 = lane & 3;
    const uint32_t xa = (uint32_t)((r4 & 6) << 3);

    const int e  = g_tile_e[blockIdx.x];
    const int r0 = g_tile_r[blockIdx.x];
    const int n0 = blockIdx.y * BN;

    const float* w2e = g_w2t + (size_t)e * DDIM * FDIM + (size_t)n0 * FDIM;

    const char* srcA[2]; const char* srcB[2];
    uint32_t dA[2], dB[2];
#pragma unroll
    for (int i = 0; i < 2; i++) {
        int idx = tid + i * 256;
        int row = idx >> 2, c = idx & 3;
        srcA[i] = (const char*)(g_H + (size_t)(r0 + row) * FDIM + c * 4);
        dA[i]   = row * 64 + ((c * 16) ^ ((row & 6) << 3));
        int n = idx & 127, cb = idx >> 7;
        srcB[i] = (const char*)(w2e + (size_t)n * FDIM + cb * 4);
        dB[i]   = n * 64 + ((cb * 16) ^ ((n & 6) << 3));
    }

    float acc[4][4][4];
#pragma unroll
    for (int i = 0; i < 4; i++)
#pragma unroll
        for (int j = 0; j < 4; j++)
#pragma unroll
            for (int q = 0; q < 4; q++) acc[i][j][q] = 0.f;

    const int KS = FDIM / BK;   // 256

#define G2_ISSUE(s)                                                            \
    do {                                                                       \
        uint32_t base_ = sb + 1024 + ((s) % 3) * STAGE2_SZ;                    \
        size_t off_ = (size_t)(s) * 64;                                        \
        _Pragma("unroll")                                                      \
        for (int i_ = 0; i_ < 2; i_++) {                                       \
            CP_ASYNC16(base_ + dA[i_],         srcA[i_] + off_);               \
            CP_ASYNC16(base_ + 8192 + dB[i_],  srcB[i_] + off_);               \
        }                                                                      \
    } while (0)

    G2_ISSUE(0); CP_COMMIT();
    G2_ISSUE(1); CP_COMMIT();

    for (int ks = 0; ks < KS; ks++) {
        CP_WAIT1();
        __syncthreads();
        if (ks + 2 < KS) G2_ISSUE(ks + 2);
        CP_COMMIT();

        const uint32_t sA = sb + 1024 + (ks % 3) * STAGE2_SZ;
        const uint32_t sB = sA + 8192;
#pragma unroll
        for (int k8 = 0; k8 < 2; k8++) {
            const uint32_t k0 = (uint32_t)((k8 * 8 + c4) * 4);
            const uint32_t k1 = k0 + 16;
            uint32_t a[4][4];
#pragma unroll
            for (int mt = 0; mt < 4; mt++) {
                uint32_t rowb = sA + (uint32_t)((wm * 64 + mt * 16 + r4) * 64);
                a[mt][0] = lds32(rowb + (k0 ^ xa));
                a[mt][1] = lds32(rowb + 512 + (k0 ^ xa));
                a[mt][2] = lds32(rowb + (k1 ^ xa));
                a[mt][3] = lds32(rowb + 512 + (k1 ^ xa));
            }
#pragma unroll
            for (int nt = 0; nt < 4; nt++) {
                uint32_t nrow = (uint32_t)((wn * 32 + nt * 8 + r4) * 64);
                uint32_t b0 = lds32(sB + nrow + (k0 ^ xa));
                uint32_t b1 = lds32(sB + nrow + (k1 ^ xa));
#pragma unroll
                for (int mt = 0; mt < 4; mt++) mma8(acc[mt][nt], a[mt], b0, b1);
            }
        }
    }

#pragma unroll
    for (int mt = 0; mt < 4; mt++) {
#pragma unroll
        for (int nt = 0; nt < 4; nt++) {
#pragma unroll
            for (int half = 0; half < 2; half++) {
                int r = r0 + wm * 64 + mt * 16 + r4 + half * 8;
                int cgl = n0 + wn * 32 + nt * 8 + 2 * c4;
                float2 o;
                o.x = acc[mt][nt][2 * half];
                o.y = acc[mt][nt][2 * half + 1];
                *(float2*)(g_Y + (size_t)r * DDIM + cgl) = o;
            }
        }
    }
}

// ---------------------------------------------------------------------------
// K7: combine — out[t] = w0*Y[row0] + w1*Y[row1]
// ---------------------------------------------------------------------------
__global__ void combine_kernel(float* __restrict__ out) {
    int t = blockIdx.x;
    int d = threadIdx.x * 4;
    float w0 = g_tok_w[2 * t], w1v = g_tok_w[2 * t + 1];
    int   r0 = g_tok_row[2 * t], r1 = g_tok_row[2 * t + 1];
    const float4 a = *(const float4*)(g_Y + (size_t)r0 * DDIM + d);
    const float4 b = *(const float4*)(g_Y + (size_t)r1 * DDIM + d);
    float4 o;
    o.x = w0 * a.x + w1v * b.x;
    o.y = w0 * a.y + w1v * b.y;
    o.z = w0 * a.z + w1v * b.z;
    o.w = w0 * a.w + w1v * b.w;
    *(float4*)(out + (size_t)t * DDIM + d) = o;
}

// ---------------------------------------------------------------------------
// Launcher
// ---------------------------------------------------------------------------
extern "C" void kernel_launch(void* const* d_in, const int* in_sizes, int n_in,
                              void* d_out, int out_size) {
    const float* x  = (const float*)d_in[0];
    const float* rw = (const float*)d_in[1];
    const float* rb = (const float*)d_in[2];
    const float* w1 = (const float*)d_in[3];
    const float* w2 = (const float*)d_in[4];
    const float* w3 = (const float*)d_in[5];
    float* out = (float*)d_out;

    static float* w1t_p = nullptr;
    if (!w1t_p) {  // resolve device-symbol addresses once (host-side, no alloc)
        cudaGetSymbolAddress((void**)&w1t_p, g_w1t);
    }

    cudaFuncSetAttribute(gemm1_kernel, cudaFuncAttributeMaxDynamicSharedMemorySize, SMEM1_SZ);
    cudaFuncSetAttribute(gemm2_kernel, cudaFuncAttributeMaxDynamicSharedMemorySize, SMEM2_SZ);

    float *w1t, *w3t, *w2t;
    cudaGetSymbolAddress((void**)&w1t, g_w1t);
    cudaGetSymbolAddress((void**)&w3t, g_w3t);
    cudaGetSymbolAddress((void**)&w2t, g_w2t);

    init_kernel<<<1, 32>>>();
    convx_kernel<<<(T_TOKENS * DDIM / 4) / 256, 256>>>(x);
    transpose_kernel<<<dim3(FDIM / 32, DDIM / 32, NEXP), dim3(32, 8)>>>(w1, w1t, DDIM, FDIM);
    transpose_kernel<<<dim3(FDIM / 32, DDIM / 32, NEXP), dim3(32, 8)>>>(w3, w3t, DDIM, FDIM);
    transpose_kernel<<<dim3(DDIM / 32, FDIM / 32, NEXP), dim3(32, 8)>>>(w2, w2t, FDIM, DDIM);
    router_kernel<<<(T_TOKENS * 32) / 256, 256>>>(x, rw, rb);
    scan_kernel<<<1, 1>>>();
    scatter_kernel<<<T_TOKENS / 256, 256>>>();
    gemm1_kernel<<<dim3(MAX_MT, FDIM / BN), 256, SMEM1_SZ>>>();
    gemm2_kernel<<<dim3(MAX_MT, DDIM / BN), 256, SMEM2_SZ>>>();
    combine_kernel<<<T_TOKENS, 256>>>(out);
}

// round 5
// speedup vs baseline: 1.8042x; 1.3706x over previous
#include <cuda_runtime.h>
#include <cstdint>

// ---------------------------------------------------------------------------
// Problem constants
// ---------------------------------------------------------------------------
#define T_TOKENS 4096
#define DDIM 1024
#define FDIM 4096
#define NEXP 8
#define BM 128
#define BN 128
#define BK 32
#define MAX_MT 72
#define ROWS_CAP (MAX_MT * 128)

// ---------------------------------------------------------------------------
// Device scratch
// ---------------------------------------------------------------------------
__device__ int   g_cnt[NEXP];
__device__ int   g_cur[NEXP];
__device__ int   g_done;
__device__ int   g_nmt;
__device__ int   g_tile_e[MAX_MT];
__device__ int   g_tile_r[MAX_MT];
__device__ int   g_row_token[ROWS_CAP];
__device__ int   g_tok_e[T_TOKENS * 2];
__device__ int   g_tok_row[T_TOKENS * 2];
__device__ float g_tok_w[T_TOKENS * 2];
__device__ float g_H[(size_t)ROWS_CAP * FDIM];          // SwiGLU intermediate (tf32-rounded)
__device__ float g_Y[(size_t)ROWS_CAP * DDIM];          // per-(token,expert) outputs
__device__ float g_xt[(size_t)T_TOKENS * DDIM];         // x, tf32-rounded
__device__ float g_w1t[(size_t)NEXP * DDIM * FDIM];     // w1^T [E][F][D], rounded
__device__ float g_w3t[(size_t)NEXP * DDIM * FDIM];     // w3^T [E][F][D], rounded
__device__ float g_w2t[(size_t)NEXP * DDIM * FDIM];     // w2^T [E][D][F], rounded

// ---------------------------------------------------------------------------
// Helpers
// ---------------------------------------------------------------------------
__device__ __forceinline__ uint32_t smem_u32(const void* p) {
    uint32_t a;
    asm("{ .reg .u64 t; cvta.to.shared.u64 t, %1; cvt.u32.u64 %0, t; }" : "=r"(a) : "l"(p));
    return a;
}
__device__ __forceinline__ uint32_t tf32u(float f) {   // round-to-nearest tf32 (bits)
    uint32_t u = __float_as_uint(f);
    asm("cvt.rna.tf32.f32 %0, %0;" : "+r"(u));
    return u;
}
__device__ __forceinline__ uint32_t lds32(uint32_t a) {
    uint32_t v;
    asm volatile("ld.shared.b32 %0, [%1];" : "=r"(v) : "r"(a));
    return v;
}
__device__ __forceinline__ void mma8(float* d, const uint32_t* a, uint32_t b0, uint32_t b1) {
    asm volatile(
        "mma.sync.aligned.m16n8k8.row.col.f32.tf32.tf32.f32 "
        "{%0,%1,%2,%3}, {%4,%5,%6,%7}, {%8,%9}, {%0,%1,%2,%3};"
        : "+f"(d[0]), "+f"(d[1]), "+f"(d[2]), "+f"(d[3])
        : "r"(a[0]), "r"(a[1]), "r"(a[2]), "r"(a[3]), "r"(b0), "r"(b1));
}
#define CP_ASYNC16(dst, src) \
    asm volatile("cp.async.cg.shared.global [%0], [%1], 16;" :: "r"(dst), "l"(src))
#define CP_COMMIT() asm volatile("cp.async.commit_group;" ::: "memory")
#define CP_WAIT1()  asm volatile("cp.async.wait_group 1;" ::: "memory")

// Region format: 128 rows x 32 floats, stored as two 8KB sub-tiles of
// [row][16 floats] (64B rows, SW64 swizzle). Conflict-free for both the
// cp.async stores and the fragment LDS (verified R3/R4).
#define REGION_SZ 16384
#define STAGE1_SZ 49152   // A + B1 + B3
#define STAGE2_SZ 32768   // A + B
#define SMEM1_SZ (1024 + 3 * STAGE1_SZ)
#define SMEM2_SZ (1024 + 3 * STAGE2_SZ)

// ---------------------------------------------------------------------------
// L1: convx + init — round x to tf32, zero counters
// ---------------------------------------------------------------------------
__global__ void convx_init_kernel(const float* __restrict__ x) {
    int i = blockIdx.x * blockDim.x + threadIdx.x;
    if (blockIdx.x == 0) {
        if (threadIdx.x < NEXP) g_cnt[threadIdx.x] = 0;
        if (threadIdx.x == NEXP) g_done = 0;
    }
    float4 v = ((const float4*)x)[i];
    uint4 o;
    o.x = tf32u(v.x); o.y = tf32u(v.y); o.z = tf32u(v.z); o.w = tf32u(v.w);
    ((uint4*)g_xt)[i] = o;
}

// ---------------------------------------------------------------------------
// L2: fused router + scan + scatter (last-CTA pattern)
// 32 CTAs x 256 threads; warp w handles 16 tokens.
// ---------------------------------------------------------------------------
__global__ void __launch_bounds__(256)
router_fused_kernel(const float* __restrict__ x, const float* __restrict__ rw,
                    const float* __restrict__ rb) {
    __shared__ float s_rw[NEXP * DDIM];
    __shared__ int s_last;
    const int tid = threadIdx.x, wid = tid >> 5, lane = tid & 31;

    for (int i = tid; i < NEXP * DDIM / 2; i += 256)
        ((float2*)s_rw)[i] = ((const float2*)rw)[i];
    __syncthreads();

    const int tbase = blockIdx.x * 128 + wid * 16;
    for (int j = 0; j < 16; j++) {
        const int t = tbase + j;
        const float* xt = x + (size_t)t * DDIM;
        float acc[NEXP];
#pragma unroll
        for (int e = 0; e < NEXP; e++) acc[e] = 0.f;
        for (int i = lane; i < DDIM; i += 32) {
            float xv = xt[i];
#pragma unroll
            for (int e = 0; e < NEXP; e++) acc[e] += xv * s_rw[e * DDIM + i];
        }
#pragma unroll
        for (int off = 16; off; off >>= 1)
#pragma unroll
            for (int e = 0; e < NEXP; e++) acc[e] += __shfl_xor_sync(0xffffffffu, acc[e], off);
        if (lane == 0) {
#pragma unroll
            for (int e = 0; e < NEXP; e++) acc[e] += rb[e];
            int e0 = 0; float l0 = acc[0];
#pragma unroll
            for (int e = 1; e < NEXP; e++) if (acc[e] > l0) { l0 = acc[e]; e0 = e; }
            int e1 = (e0 == 0) ? 1 : 0; float l1 = acc[e1];
#pragma unroll
            for (int e = 0; e < NEXP; e++)
                if (e != e0 && acc[e] > l1) { l1 = acc[e]; e1 = e; }
            float w0 = 1.f / (1.f + __expf(l1 - l0));
            g_tok_e[2 * t] = e0;  g_tok_e[2 * t + 1] = e1;
            g_tok_w[2 * t] = w0;  g_tok_w[2 * t + 1] = 1.f - w0;
            atomicAdd(&g_cnt[e0], 1);
            atomicAdd(&g_cnt[e1], 1);
        }
    }

    // completion detection
    __syncthreads();
    if (tid == 0) {
        __threadfence();
        int v = atomicAdd(&g_done, 1);
        s_last = (v == (int)gridDim.x - 1);
    }
    __syncthreads();
    if (!s_last) return;
    __threadfence();

    // scan (thread 0 of last CTA)
    if (tid == 0) {
        int base = 0, nt = 0;
        for (int e = 0; e < NEXP; e++) {
            g_cur[e] = base;
            int tiles = (g_cnt[e] + 127) >> 7;
            for (int i = 0; i < tiles; i++) { g_tile_e[nt] = e; g_tile_r[nt] = base + i * 128; nt++; }
            base += tiles << 7;
        }
        g_nmt = nt;
        g_done = 0;   // reset for next graph replay
    }
    __syncthreads();

    // scatter (whole last CTA)
    for (int t = tid; t < T_TOKENS; t += 256) {
#pragma unroll
        for (int k = 0; k < 2; k++) {
            int e = g_tok_e[2 * t + k];
            int r = atomicAdd(&g_cur[e], 1);
            g_row_token[r] = t;
            g_tok_row[2 * t + k] = r;
        }
    }
}

// ---------------------------------------------------------------------------
// L3/L5: transpose + round: src [Z][R][C] -> dst [Z][C][R]
// transpose13: z 0..15 covers w1 (z<8) and w3 (z>=8)
// ---------------------------------------------------------------------------
__global__ void transpose13_kernel(const float* __restrict__ w1, const float* __restrict__ w3,
                                   float* __restrict__ w1t, float* __restrict__ w3t) {
    __shared__ float t[32][33];
    const int zz = blockIdx.z;
    const float* src = (zz < NEXP) ? w1 : w3;
    float* dst = (zz < NEXP) ? w1t : w3t;
    const size_t mo = (size_t)(zz & 7) * DDIM * FDIM;
    const int c0 = blockIdx.x * 32, r0 = blockIdx.y * 32;
    const int tx = threadIdx.x, ty = threadIdx.y;
#pragma unroll
    for (int i = 0; i < 32; i += 8)
        t[ty + i][tx] = src[mo + (size_t)(r0 + ty + i) * FDIM + c0 + tx];
    __syncthreads();
#pragma unroll
    for (int i = 0; i < 32; i += 8)
        dst[mo + (size_t)(c0 + ty + i) * DDIM + r0 + tx] = __uint_as_float(tf32u(t[tx][ty + i]));
}

__global__ void transpose2_kernel(const float* __restrict__ src, float* __restrict__ dst) {
    __shared__ float t[32][33];
    const size_t mo = (size_t)blockIdx.z * DDIM * FDIM;
    const int c0 = blockIdx.x * 32, r0 = blockIdx.y * 32;
    const int tx = threadIdx.x, ty = threadIdx.y;
#pragma unroll
    for (int i = 0; i < 32; i += 8)
        t[ty + i][tx] = src[mo + (size_t)(r0 + ty + i) * DDIM + c0 + tx];
    __syncthreads();
#pragma unroll
    for (int i = 0; i < 32; i += 8)
        dst[mo + (size_t)(c0 + ty + i) * FDIM + r0 + tx] = __uint_as_float(tf32u(t[tx][ty + i]));
}

// ---------------------------------------------------------------------------
// L4: grouped GEMM1 — H = silu(X@w1) * (X@w3)
// 128x128 CTA tile, BK=32, 8 warps (2Mx4N), 3-stage cp.async pipeline.
// ---------------------------------------------------------------------------
__global__ void __launch_bounds__(256, 1)
gemm1_kernel() {
    if (blockIdx.x >= g_nmt) return;
    extern __shared__ char smem[];
    const uint32_t sb = smem_u32(smem);
    const int tid = threadIdx.x, wid = tid >> 5, lane = tid & 31;
    const int wm = wid >> 2, wn = wid & 3;
    const int r4 = lane >> 2, c4 = lane & 3;
    const uint32_t xa = (uint32_t)((r4 & 6) << 3);

    const int e  = g_tile_e[blockIdx.x];
    const int r0 = g_tile_r[blockIdx.x];
    const int n0 = blockIdx.y * BN;

    int* s_tok = (int*)smem;
    if (tid < 128) {
        int t = g_row_token[r0 + tid];
        s_tok[tid] = ((unsigned)t < T_TOKENS) ? t : 0;
    }
    __syncthreads();

    const float* w1e = g_w1t + (size_t)e * FDIM * DDIM + (size_t)n0 * DDIM;
    const float* w3e = g_w3t + (size_t)e * FDIM * DDIM + (size_t)n0 * DDIM;

    // per-thread cp.async chunks: 4 per region (region = 128 rows x 128B)
    const char* srcA[4]; const char* srcB1[4]; const char* srcB3[4];
    uint32_t dOf[4];
#pragma unroll
    for (int i = 0; i < 4; i++) {
        int idx = tid + i * 256;
        int row = idx >> 3, c = idx & 7;
        dOf[i] = (uint32_t)((c >> 2) * 8192 + row * 64 + (((c & 3) * 16) ^ ((row & 6) << 3)));
        srcA[i]  = (const char*)(g_xt + (size_t)s_tok[row] * DDIM + c * 4);
        srcB1[i] = (const char*)(w1e + (size_t)row * DDIM + c * 4);
        srcB3[i] = (const char*)(w3e + (size_t)row * DDIM + c * 4);
    }

    float accU[4][4][4], accV[4][4][4];
#pragma unroll
    for (int i = 0; i < 4; i++)
#pragma unroll
        for (int j = 0; j < 4; j++)
#pragma unroll
            for (int q = 0; q < 4; q++) { accU[i][j][q] = 0.f; accV[i][j][q] = 0.f; }

    const int KS = DDIM / BK;   // 32

#define G1_ISSUE(s)                                                            \
    do {                                                                       \
        uint32_t base_ = sb + 1024 + ((s) % 3) * STAGE1_SZ;                    \
        size_t off_ = (size_t)(s) * 128;                                       \
        _Pragma("unroll")                                                      \
        for (int i_ = 0; i_ < 4; i_++) {                                       \
            CP_ASYNC16(base_ + dOf[i_],             srcA[i_]  + off_);         \
            CP_ASYNC16(base_ + 16384 + dOf[i_],     srcB1[i_] + off_);         \
            CP_ASYNC16(base_ + 32768 + dOf[i_],     srcB3[i_] + off_);         \
        }                                                                      \
    } while (0)

    G1_ISSUE(0); CP_COMMIT();
    G1_ISSUE(1); CP_COMMIT();

    for (int ks = 0; ks < KS; ks++) {
        CP_WAIT1();
        __syncthreads();
        if (ks + 2 < KS) G1_ISSUE(ks + 2);
        CP_COMMIT();

        const uint32_t st = sb + 1024 + (ks % 3) * STAGE1_SZ;
#pragma unroll
        for (int k8 = 0; k8 < 4; k8++) {
            const uint32_t sub = (uint32_t)((k8 >> 1) * 8192);
            const uint32_t sA  = st + sub;
            const uint32_t sB1 = st + 16384 + sub;
            const uint32_t sB3 = st + 32768 + sub;
            const uint32_t k0 = (uint32_t)((((k8 & 1) * 8) + c4) * 4);
            const uint32_t k1 = k0 + 16;
            uint32_t a[4][4];
#pragma unroll
            for (int mt = 0; mt < 4; mt++) {
                uint32_t rowb = sA + (uint32_t)((wm * 64 + mt * 16 + r4) * 64);
                a[mt][0] = lds32(rowb + (k0 ^ xa));
                a[mt][1] = lds32(rowb + 512 + (k0 ^ xa));
                a[mt][2] = lds32(rowb + (k1 ^ xa));
                a[mt][3] = lds32(rowb + 512 + (k1 ^ xa));
            }
#pragma unroll
            for (int nt = 0; nt < 4; nt++) {
                uint32_t nrow = (uint32_t)((wn * 32 + nt * 8 + r4) * 64);
                uint32_t b0 = lds32(sB1 + nrow + (k0 ^ xa));
                uint32_t b1 = lds32(sB1 + nrow + (k1 ^ xa));
                uint32_t d0 = lds32(sB3 + nrow + (k0 ^ xa));
                uint32_t d1 = lds32(sB3 + nrow + (k1 ^ xa));
#pragma unroll
                for (int mt = 0; mt < 4; mt++) {
                    mma8(accU[mt][nt], a[mt], b0, b1);
                    mma8(accV[mt][nt], a[mt], d0, d1);
                }
            }
        }
    }

    // epilogue: h = silu(u)*v, tf32-rounded, write g_H
#pragma unroll
    for (int mt = 0; mt < 4; mt++) {
#pragma unroll
        for (int nt = 0; nt < 4; nt++) {
#pragma unroll
            for (int half = 0; half < 2; half++) {
                int r = r0 + wm * 64 + mt * 16 + r4 + half * 8;
                int cgl = n0 + wn * 32 + nt * 8 + 2 * c4;
                float u0 = accU[mt][nt][2 * half],     v0 = accV[mt][nt][2 * half];
                float u1 = accU[mt][nt][2 * half + 1], v1 = accV[mt][nt][2 * half + 1];
                float2 o;
                o.x = __uint_as_float(tf32u(u0 / (1.f + __expf(-u0)) * v0));
                o.y = __uint_as_float(tf32u(u1 / (1.f + __expf(-u1)) * v1));
                *(float2*)(g_H + (size_t)r * FDIM + cgl) = o;
            }
        }
    }
}

// ---------------------------------------------------------------------------
// L6: grouped GEMM2 — Y = H @ w2   (BK=32, occupancy 2)
// ---------------------------------------------------------------------------
__global__ void __launch_bounds__(256, 2)
gemm2_kernel() {
    if (blockIdx.x >= g_nmt) return;
    extern __shared__ char smem[];
    const uint32_t sb = smem_u32(smem);
    const int tid = threadIdx.x, wid = tid >> 5, lane = tid & 31;
    const int wm = wid >> 2, wn = wid & 3;
    const int r4 = lane >> 2, c4 = lane & 3;
    const uint32_t xa = (uint32_t)((r4 & 6) << 3);

    const int e  = g_tile_e[blockIdx.x];
    const int r0 = g_tile_r[blockIdx.x];
    const int n0 = blockIdx.y * BN;

    const float* w2e = g_w2t + (size_t)e * DDIM * FDIM + (size_t)n0 * FDIM;

    const char* srcA[4]; const char* srcB[4];
    uint32_t dOf[4];
#pragma unroll
    for (int i = 0; i < 4; i++) {
        int idx = tid + i * 256;
        int row = idx >> 3, c = idx & 7;
        dOf[i] = (uint32_t)((c >> 2) * 8192 + row * 64 + (((c & 3) * 16) ^ ((row & 6) << 3)));
        srcA[i] = (const char*)(g_H + (size_t)(r0 + row) * FDIM + c * 4);
        srcB[i] = (const char*)(w2e + (size_t)row * FDIM + c * 4);
    }

    float acc[4][4][4];
#pragma unroll
    for (int i = 0; i < 4; i++)
#pragma unroll
        for (int j = 0; j < 4; j++)
#pragma unroll
            for (int q = 0; q < 4; q++) acc[i][j][q] = 0.f;

    const int KS = FDIM / BK;   // 128

#define G2_ISSUE(s)                                                            \
    do {                                                                       \
        uint32_t base_ = sb + 1024 + ((s) % 3) * STAGE2_SZ;                    \
        size_t off_ = (size_t)(s) * 128;                                       \
        _Pragma("unroll")                                                      \
        for (int i_ = 0; i_ < 4; i_++) {                                       \
            CP_ASYNC16(base_ + dOf[i_],          srcA[i_] + off_);             \
            CP_ASYNC16(base_ + 16384 + dOf[i_],  srcB[i_] + off_);             \
        }                                                                      \
    } while (0)

    G2_ISSUE(0); CP_COMMIT();
    G2_ISSUE(1); CP_COMMIT();

    for (int ks = 0; ks < KS; ks++) {
        CP_WAIT1();
        __syncthreads();
        if (ks + 2 < KS) G2_ISSUE(ks + 2);
        CP_COMMIT();

        const uint32_t st = sb + 1024 + (ks % 3) * STAGE2_SZ;
#pragma unroll
        for (int k8 = 0; k8 < 4; k8++) {
            const uint32_t sub = (uint32_t)((k8 >> 1) * 8192);
            const uint32_t sA = st + sub;
            const uint32_t sB = st + 16384 + sub;
            const uint32_t k0 = (uint32_t)((((k8 & 1) * 8) + c4) * 4);
            const uint32_t k1 = k0 + 16;
            uint32_t a[4][4];
#pragma unroll
            for (int mt = 0; mt < 4; mt++) {
                uint32_t rowb = sA + (uint32_t)((wm * 64 + mt * 16 + r4) * 64);
                a[mt][0] = lds32(rowb + (k0 ^ xa));
                a[mt][1] = lds32(rowb + 512 + (k0 ^ xa));
                a[mt][2] = lds32(rowb + (k1 ^ xa));
                a[mt][3] = lds32(rowb + 512 + (k1 ^ xa));
            }
#pragma unroll
            for (int nt = 0; nt < 4; nt++) {
                uint32_t nrow = (uint32_t)((wn * 32 + nt * 8 + r4) * 64);
                uint32_t b0 = lds32(sB + nrow + (k0 ^ xa));
                uint32_t b1 = lds32(sB + nrow + (k1 ^ xa));
#pragma unroll
                for (int mt = 0; mt < 4; mt++) mma8(acc[mt][nt], a[mt], b0, b1);
            }
        }
    }

#pragma unroll
    for (int mt = 0; mt < 4; mt++) {
#pragma unroll
        for (int nt = 0; nt < 4; nt++) {
#pragma unroll
            for (int half = 0; half < 2; half++) {
                int r = r0 + wm * 64 + mt * 16 + r4 + half * 8;
                int cgl = n0 + wn * 32 + nt * 8 + 2 * c4;
                float2 o;
                o.x = acc[mt][nt][2 * half];
                o.y = acc[mt][nt][2 * half + 1];
                *(float2*)(g_Y + (size_t)r * DDIM + cgl) = o;
            }
        }
    }
}

// ---------------------------------------------------------------------------
// L7: combine — out[t] = w0*Y[row0] + w1*Y[row1]
// ---------------------------------------------------------------------------
__global__ void combine_kernel(float* __restrict__ out) {
    int t = blockIdx.x;
    int d = threadIdx.x * 4;
    float w0 = g_tok_w[2 * t], w1v = g_tok_w[2 * t + 1];
    int   r0 = g_tok_row[2 * t], r1 = g_tok_row[2 * t + 1];
    const float4 a = *(const float4*)(g_Y + (size_t)r0 * DDIM + d);
    const float4 b = *(const float4*)(g_Y + (size_t)r1 * DDIM + d);
    float4 o;
    o.x = w0 * a.x + w1v * b.x;
    o.y = w0 * a.y + w1v * b.y;
    o.z = w0 * a.z + w1v * b.z;
    o.w = w0 * a.w + w1v * b.w;
    *(float4*)(out + (size_t)t * DDIM + d) = o;
}

// ---------------------------------------------------------------------------
// Launcher — gemm1 is the 4th launch (profiler capture target)
// ---------------------------------------------------------------------------
extern "C" void kernel_launch(void* const* d_in, const int* in_sizes, int n_in,
                              void* d_out, int out_size) {
    const float* x  = (const float*)d_in[0];
    const float* rw = (const float*)d_in[1];
    const float* rb = (const float*)d_in[2];
    const float* w1 = (const float*)d_in[3];
    const float* w2 = (const float*)d_in[4];
    const float* w3 = (const float*)d_in[5];
    float* out = (float*)d_out;

    cudaFuncSetAttribute(gemm1_kernel, cudaFuncAttributeMaxDynamicSharedMemorySize, SMEM1_SZ);
    cudaFuncSetAttribute(gemm2_kernel, cudaFuncAttributeMaxDynamicSharedMemorySize, SMEM2_SZ);

    float *w1t, *w3t, *w2t;
    cudaGetSymbolAddress((void**)&w1t, g_w1t);
    cudaGetSymbolAddress((void**)&w3t, g_w3t);
    cudaGetSymbolAddress((void**)&w2t, g_w2t);

    convx_init_kernel<<<(T_TOKENS * DDIM / 4) / 256, 256>>>(x);
    router_fused_kernel<<<32, 256>>>(x, rw, rb);
    transpose13_kernel<<<dim3(FDIM / 32, DDIM / 32, 2 * NEXP), dim3(32, 8)>>>(w1, w3, w1t, w3t);
    gemm1_kernel<<<dim3(MAX_MT, FDIM / BN), 256, SMEM1_SZ>>>();
    transpose2_kernel<<<dim3(DDIM / 32, FDIM / 32, NEXP), dim3(32, 8)>>>(w2, w2t);
    gemm2_kernel<<<dim3(MAX_MT, DDIM / BN), 256, SMEM2_SZ>>>();
    combine_kernel<<<T_TOKENS, 256>>>(out);
}